// round 4
// baseline (speedup 1.0000x reference)
#include <cuda_runtime.h>
#include <math.h>

#define Bdim 64
#define Sdim 512
#define Fdim 512
#define Hdim 1024

// ---------------- scratch (static device globals; no runtime allocation) ----
__device__ float g_xp[(size_t)Bdim * Sdim * Hdim];   // 128 MB: x-projection buffer
__device__ float g_h1[(size_t)Bdim * Sdim * Hdim];   // 128 MB: layer-1 hidden sequence
__device__ float g_hbuf[2][Bdim * Hdim];             // double-buffered hidden state
__device__ unsigned g_bar_count = 0;
__device__ volatile unsigned g_bar_gen = 0;

static __device__ __forceinline__ unsigned smem_u32(const void* p) {
    return (unsigned)__cvta_generic_to_shared(p);
}

// ---------------- grid barrier (all 128 CTAs co-resident; grid <= 148) ------
static __device__ __forceinline__ void grid_sync(int nblocks) {
    __syncthreads();
    if (threadIdx.x == 0) {
        __threadfence();
        unsigned g = g_bar_gen;
        if (atomicAdd(&g_bar_count, 1u) == (unsigned)(nblocks - 1)) {
            g_bar_count = 0;
            __threadfence();
            g_bar_gen = g + 1;
        } else {
            while (g_bar_gen == g) {}
        }
        __threadfence();
    }
    __syncthreads();
}

// ============================================================================
// Phase GEMM: out[m][n] = sum_k A[m][k] * Wt[n][k] + ba[n] + bb[n]
// M = 32768, N = 1024. CTA tile 128x64, K-tile 16, 256 threads, 8x4/thread.
// ============================================================================
template <int K>
__global__ void __launch_bounds__(256) xproj_kernel(
    const float* __restrict__ A, const float* __restrict__ Wt,
    const float* __restrict__ ba, const float* __restrict__ bb,
    float* __restrict__ out)
{
    __shared__ float As[16][128];
    __shared__ float Bs[16][68];

    const int tid = threadIdx.x;
    const int tn  = tid & 15;    // N tile pos (4 cols each)
    const int tmg = tid >> 4;    // M tile pos (8 rows each)
    const int m0  = blockIdx.y * 128;
    const int n0  = blockIdx.x * 64;

    // A-tile loader indices: 512 float4 per tile -> 2 per thread
    const int arow0 = tid >> 1;            // using idx = tid*... recompute below
    (void)arow0;

    float acc[8][4];
#pragma unroll
    for (int i = 0; i < 8; i++)
#pragma unroll
        for (int j = 0; j < 4; j++) acc[i][j] = 0.0f;

    const int NK = K / 16;

    // prefetch registers
    float4 pa0, pa1, pb0;
    {
        int i0 = tid, i1 = tid + 256;
        int r0 = i0 >> 2, q0 = i0 & 3;
        int r1 = i1 >> 2, q1 = i1 & 3;
        pa0 = *(const float4*)&A[(size_t)(m0 + r0) * K + q0 * 4];
        pa1 = *(const float4*)&A[(size_t)(m0 + r1) * K + q1 * 4];
        int br = tid >> 2, bq = tid & 3;
        pb0 = *(const float4*)&Wt[(size_t)(n0 + br) * K + bq * 4];
    }

    for (int kt = 0; kt < NK; kt++) {
        __syncthreads();  // previous compute finished reading smem
        // store staged tiles (transposed: [k][m] / [k][n])
        {
            int i0 = tid, i1 = tid + 256;
            int r0 = i0 >> 2, q0 = i0 & 3;
            int r1 = i1 >> 2, q1 = i1 & 3;
            As[q0 * 4 + 0][r0] = pa0.x; As[q0 * 4 + 1][r0] = pa0.y;
            As[q0 * 4 + 2][r0] = pa0.z; As[q0 * 4 + 3][r0] = pa0.w;
            As[q1 * 4 + 0][r1] = pa1.x; As[q1 * 4 + 1][r1] = pa1.y;
            As[q1 * 4 + 2][r1] = pa1.z; As[q1 * 4 + 3][r1] = pa1.w;
            int br = tid >> 2, bq = tid & 3;
            Bs[bq * 4 + 0][br] = pb0.x; Bs[bq * 4 + 1][br] = pb0.y;
            Bs[bq * 4 + 2][br] = pb0.z; Bs[bq * 4 + 3][br] = pb0.w;
        }
        __syncthreads();
        // prefetch next tile
        if (kt + 1 < NK) {
            int kb = (kt + 1) * 16;
            int i0 = tid, i1 = tid + 256;
            int r0 = i0 >> 2, q0 = i0 & 3;
            int r1 = i1 >> 2, q1 = i1 & 3;
            pa0 = *(const float4*)&A[(size_t)(m0 + r0) * K + kb + q0 * 4];
            pa1 = *(const float4*)&A[(size_t)(m0 + r1) * K + kb + q1 * 4];
            int br = tid >> 2, bq = tid & 3;
            pb0 = *(const float4*)&Wt[(size_t)(n0 + br) * K + kb + bq * 4];
        }
        // compute 16 k-steps
#pragma unroll
        for (int k = 0; k < 16; k++) {
            float4 av0 = *(const float4*)&As[k][tmg * 8];
            float4 av1 = *(const float4*)&As[k][tmg * 8 + 4];
            float4 bv  = *(const float4*)&Bs[k][tn * 4];
            float am[8] = {av0.x, av0.y, av0.z, av0.w, av1.x, av1.y, av1.z, av1.w};
            float bn[4] = {bv.x, bv.y, bv.z, bv.w};
#pragma unroll
            for (int i = 0; i < 8; i++)
#pragma unroll
                for (int j = 0; j < 4; j++) acc[i][j] += am[i] * bn[j];
        }
    }

    // epilogue with bias
    float4 b1 = *(const float4*)&ba[n0 + tn * 4];
    float4 b2 = *(const float4*)&bb[n0 + tn * 4];
    float bias[4] = {b1.x + b2.x, b1.y + b2.y, b1.z + b2.z, b1.w + b2.w};
#pragma unroll
    for (int i = 0; i < 8; i++) {
        float4 o;
        o.x = acc[i][0] + bias[0];
        o.y = acc[i][1] + bias[1];
        o.z = acc[i][2] + bias[2];
        o.w = acc[i][3] + bias[3];
        *(float4*)&out[(size_t)(m0 + tmg * 8 + i) * Hdim + n0 + tn * 4] = o;
    }
}

// ============================================================================
// Recurrence: persistent kernel, 128 CTAs x 256 threads.
// CTA owns 8 output neurons (W slice in SMEM). Per step:
//   h_new[b][j] = tanh(xp[b][t][j] + sum_k h_old[b][k] * Whh[j][k])
// Threads: kc = tid>>4 (16 K-chunks), bt = (tid>>1)&7 (8 b-groups of 8),
//          jt = tid&1 (2 j-groups of 4). Per-thread tile: 8b x 4j.
// ============================================================================
#define RNN_W_ROW 1028
#define RNN_HS    (64 * 128)         // one h stage buffer (floats)
#define RNN_SMEM_FLOATS (8 * RNN_W_ROW + 2 * RNN_HS + 512 * 17)
#define RNN_SMEM_BYTES  (RNN_SMEM_FLOATS * 4)

static __device__ __forceinline__ void stage_h(const float* __restrict__ hin,
                                               int kt, float* dst, int tid) {
#pragma unroll
    for (int r = 0; r < 8; r++) {
        int idx = r * 256 + tid;          // 2048 float4
        int b = idx >> 5;                 // 0..63
        int cq = idx & 31;                // float4 col in 128-wide tile
        int scq = cq ^ ((b >> 3) & 7);    // XOR swizzle kills b-stride conflicts
        unsigned d = smem_u32(&dst[b * 128 + (scq << 2)]);
        const float* s = &hin[b * Hdim + kt * 128 + (cq << 2)];
        asm volatile("cp.async.cg.shared.global [%0], [%1], 16;" ::"r"(d), "l"(s));
    }
}

__global__ void __launch_bounds__(256) rnn_kernel(
    const float* __restrict__ xp, const float* __restrict__ Whh,
    float* __restrict__ out_seq)
{
    extern __shared__ float sm[];
    float* w_s = sm;                          // [8][1028]
    float* h_s = sm + 8 * RNN_W_ROW;          // [2][64][128] (swizzled)
    float* p_s = h_s + 2 * RNN_HS;            // [512][17] partials

    const int tid = threadIdx.x;
    const int kc = tid >> 4;
    const int bt = (tid >> 1) & 7;
    const int jt = tid & 1;
    const int j0 = blockIdx.x * 8;
    const int nb = gridDim.x;

    // load W slice into SMEM (8 rows x 1024)
#pragma unroll
    for (int r = 0; r < 8; r++) {
        int f4 = r * 256 + tid;               // 2048 float4
        int j = f4 >> 8, q = f4 & 255;
        float4 v = *(const float4*)&Whh[(size_t)(j0 + j) * Hdim + q * 4];
        *(float4*)&w_s[j * RNN_W_ROW + q * 4] = v;
    }
    // zero initial hidden state slice
    if (tid < 128)
        *(float4*)&g_hbuf[0][blockIdx.x * 512 + tid * 4] = make_float4(0.f, 0.f, 0.f, 0.f);
    grid_sync(nb);

    for (int t = 0; t < Sdim; t++) {
        const float* hin = g_hbuf[t & 1];
        float* hout = g_hbuf[(t + 1) & 1];

        float acc[8][4];
#pragma unroll
        for (int i = 0; i < 8; i++)
#pragma unroll
            for (int j = 0; j < 4; j++) acc[i][j] = 0.0f;

        stage_h(hin, 0, h_s, tid);
        asm volatile("cp.async.commit_group;");

#pragma unroll 1
        for (int kt = 0; kt < 8; kt++) {
            if (kt < 7) {
                stage_h(hin, kt + 1, h_s + ((kt + 1) & 1) * RNN_HS, tid);
                asm volatile("cp.async.commit_group;");
                asm volatile("cp.async.wait_group 1;");
            } else {
                asm volatile("cp.async.wait_group 0;");
            }
            __syncthreads();

            const float* hb = h_s + (kt & 1) * RNN_HS;
#pragma unroll
            for (int f = 0; f < 2; f++) {
                int cq = kc + f * 16;                    // float4 col 0..31
                int kcol = kt * 128 + cq * 4;            // abs k for W
                float4 w0 = *(const float4*)&w_s[(jt * 4 + 0) * RNN_W_ROW + kcol];
                float4 w1 = *(const float4*)&w_s[(jt * 4 + 1) * RNN_W_ROW + kcol];
                float4 w2 = *(const float4*)&w_s[(jt * 4 + 2) * RNN_W_ROW + kcol];
                float4 w3 = *(const float4*)&w_s[(jt * 4 + 3) * RNN_W_ROW + kcol];
                int hcol = (cq ^ bt) << 2;               // matches stage swizzle
#pragma unroll
                for (int bb = 0; bb < 8; bb++) {
                    int b = bt * 8 + bb;
                    float4 hv = *(const float4*)&hb[b * 128 + hcol];
                    acc[bb][0] += hv.x * w0.x + hv.y * w0.y + hv.z * w0.z + hv.w * w0.w;
                    acc[bb][1] += hv.x * w1.x + hv.y * w1.y + hv.z * w1.z + hv.w * w1.w;
                    acc[bb][2] += hv.x * w2.x + hv.y * w2.y + hv.z * w2.z + hv.w * w2.w;
                    acc[bb][3] += hv.x * w3.x + hv.y * w3.y + hv.z * w3.z + hv.w * w3.w;
                }
            }
            __syncthreads();
        }

        // write partials: output o = b*8 + j_local, chunk kc
#pragma unroll
        for (int bb = 0; bb < 8; bb++)
#pragma unroll
            for (int jj = 0; jj < 4; jj++) {
                int o = (bt * 8 + bb) * 8 + jt * 4 + jj;
                p_s[o * 17 + kc] = acc[bb][jj];
            }
        __syncthreads();

        // reduce 16 partials, add xp, tanh, write h_new (+ sequence)
#pragma unroll
        for (int r = 0; r < 2; r++) {
            int o = tid * 2 + r;
            int b = o >> 3, jl = o & 7;
            float s = 0.0f;
#pragma unroll
            for (int c = 0; c < 16; c++) s += p_s[o * 17 + c];
            float v = tanhf(s + xp[(size_t)(b * Sdim + t) * Hdim + j0 + jl]);
            hout[b * Hdim + j0 + jl] = v;
            if (out_seq) out_seq[(size_t)(b * Sdim + t) * Hdim + j0 + jl] = v;
        }
        grid_sync(nb);
    }
}

// ============================================================================
// Final FC + sigmoid: out[b] = sigmoid(dot(h_last[b], fc_w) + fc_b)
// ============================================================================
__global__ void fc_kernel(const float* __restrict__ hlast,
                          const float* __restrict__ fcw,
                          const float* __restrict__ fcb,
                          float* __restrict__ out)
{
    __shared__ float red[8];
    int b = blockIdx.x, tid = threadIdx.x;
    float s = 0.0f;
    for (int k = tid; k < Hdim; k += 256) s += hlast[b * Hdim + k] * fcw[k];
#pragma unroll
    for (int o = 16; o; o >>= 1) s += __shfl_xor_sync(0xFFFFFFFFu, s, o);
    if ((tid & 31) == 0) red[tid >> 5] = s;
    __syncthreads();
    if (tid == 0) {
        float tot = 0.0f;
#pragma unroll
        for (int i = 0; i < 8; i++) tot += red[i];
        float logit = tot + fcb[0];
        out[b] = 1.0f / (1.0f + expf(-logit));
    }
}

// ============================================================================
extern "C" void kernel_launch(void* const* d_in, const int* in_sizes, int n_in,
                              void* d_out, int out_size)
{
    const float* x     = (const float*)d_in[0];
    const float* W_ih0 = (const float*)d_in[1];
    const float* W_hh0 = (const float*)d_in[2];
    const float* b_ih0 = (const float*)d_in[3];
    const float* b_hh0 = (const float*)d_in[4];
    const float* W_ih1 = (const float*)d_in[5];
    const float* W_hh1 = (const float*)d_in[6];
    const float* b_ih1 = (const float*)d_in[7];
    const float* b_hh1 = (const float*)d_in[8];
    const float* fc_w  = (const float*)d_in[9];
    const float* fc_b  = (const float*)d_in[10];
    float* out = (float*)d_out;

    float *xp, *h1, *hbuf;
    cudaGetSymbolAddress((void**)&xp, g_xp);
    cudaGetSymbolAddress((void**)&h1, g_h1);
    cudaGetSymbolAddress((void**)&hbuf, g_hbuf);

    cudaFuncSetAttribute(rnn_kernel, cudaFuncAttributeMaxDynamicSharedMemorySize,
                         RNN_SMEM_BYTES);

    dim3 ggrid(16, 256);  // N/64, M/128

    // layer 0
    xproj_kernel<Fdim><<<ggrid, 256>>>(x, W_ih0, b_ih0, b_hh0, xp);
    rnn_kernel<<<128, 256, RNN_SMEM_BYTES>>>(xp, W_hh0, h1);
    // layer 1
    xproj_kernel<Hdim><<<ggrid, 256>>>(h1, W_ih1, b_ih1, b_hh1, xp);
    rnn_kernel<<<128, 256, RNN_SMEM_BYTES>>>(xp, W_hh1, nullptr);
    // head (final h2 is in g_hbuf[0] since step 511 writes buffer (511+1)&1 = 0)
    fc_kernel<<<64, 256>>>(hbuf, fc_w, fc_b, out);
}

// round 5
// speedup vs baseline: 1.0289x; 1.0289x over previous
#include <cuda_runtime.h>
#include <math.h>

#define Bdim 64
#define Sdim 512
#define Fdim 512
#define Hdim 1024

typedef unsigned long long ull;

// ---------------- scratch (static device globals; no runtime allocation) ----
__device__ float g_xp[(size_t)Bdim * Sdim * Hdim];   // 128 MB: x-projection buffer
__device__ float g_h1[(size_t)Bdim * Sdim * Hdim];   // 128 MB: layer-1 hidden seq [t][b][H]
__device__ float g_hbuf[2][Hdim * Bdim];             // double-buffered hidden state [k][b]
__device__ unsigned g_bar_count = 0;
__device__ volatile unsigned g_bar_gen = 0;

static __device__ __forceinline__ unsigned smem_u32(const void* p) {
    return (unsigned)__cvta_generic_to_shared(p);
}

// ---------------- packed fp32x2 helpers (FFMA2 path, sm_100+) ---------------
static __device__ __forceinline__ void ffma2(ull& d, ull a, ull b) {
    asm("fma.rn.f32x2 %0, %1, %2, %0;" : "+l"(d) : "l"(a), "l"(b));
}
static __device__ __forceinline__ ull addf32x2(ull a, ull b) {
    ull d; asm("add.rn.f32x2 %0, %1, %2;" : "=l"(d) : "l"(a), "l"(b)); return d;
}
static __device__ __forceinline__ ull bcast2(float x) {
    ull d; unsigned r = __float_as_uint(x);
    asm("mov.b64 %0, {%1, %1};" : "=l"(d) : "r"(r)); return d;
}
static __device__ __forceinline__ float2 u2f2(ull v) {
    float2 f; asm("mov.b64 {%0, %1}, %2;" : "=f"(f.x), "=f"(f.y) : "l"(v)); return f;
}

// ---------------- grid barrier (all 128 CTAs co-resident; grid <= 148) ------
static __device__ __forceinline__ void grid_sync(int nblocks) {
    __syncthreads();
    if (threadIdx.x == 0) {
        __threadfence();
        unsigned g = g_bar_gen;
        if (atomicAdd(&g_bar_count, 1u) == (unsigned)(nblocks - 1)) {
            g_bar_count = 0;
            __threadfence();
            g_bar_gen = g + 1;
        } else {
            while (g_bar_gen == g) {}
        }
        __threadfence();
    }
    __syncthreads();
}

// ============================================================================
// Phase GEMM: out[m][n] = sum_k A[m][k] * Wt[n][k] + ba[n] + bb[n]
// M = 32768, N = 1024. CTA tile 128x64, K-tile 16, 256 threads, 8x4/thread.
// Inner loop uses fma.rn.f32x2 paired over m (pairs free from As float4 regs).
// ============================================================================
template <int K>
__global__ void __launch_bounds__(256) xproj_kernel(
    const float* __restrict__ A, const float* __restrict__ Wt,
    const float* __restrict__ ba, const float* __restrict__ bb,
    float* __restrict__ out)
{
    __shared__ float As[16][128];
    __shared__ float Bs[16][68];

    const int tid = threadIdx.x;
    const int tn  = tid & 15;    // N tile pos (4 cols each)
    const int tmg = tid >> 4;    // M tile pos (8 rows each)
    const int m0  = blockIdx.y * 128;
    const int n0  = blockIdx.x * 64;

    ull acc2[4][4];              // [m-pair][n], each = (m_even, m_odd)
#pragma unroll
    for (int i = 0; i < 4; i++)
#pragma unroll
        for (int j = 0; j < 4; j++) acc2[i][j] = 0ull;

    const int NK = K / 16;

    // prefetch registers
    float4 pa0, pa1, pb0;
    {
        int i0 = tid, i1 = tid + 256;
        int r0 = i0 >> 2, q0 = i0 & 3;
        int r1 = i1 >> 2, q1 = i1 & 3;
        pa0 = *(const float4*)&A[(size_t)(m0 + r0) * K + q0 * 4];
        pa1 = *(const float4*)&A[(size_t)(m0 + r1) * K + q1 * 4];
        int br = tid >> 2, bq = tid & 3;
        pb0 = *(const float4*)&Wt[(size_t)(n0 + br) * K + bq * 4];
    }

    for (int kt = 0; kt < NK; kt++) {
        __syncthreads();  // previous compute finished reading smem
        {
            int i0 = tid, i1 = tid + 256;
            int r0 = i0 >> 2, q0 = i0 & 3;
            int r1 = i1 >> 2, q1 = i1 & 3;
            As[q0 * 4 + 0][r0] = pa0.x; As[q0 * 4 + 1][r0] = pa0.y;
            As[q0 * 4 + 2][r0] = pa0.z; As[q0 * 4 + 3][r0] = pa0.w;
            As[q1 * 4 + 0][r1] = pa1.x; As[q1 * 4 + 1][r1] = pa1.y;
            As[q1 * 4 + 2][r1] = pa1.z; As[q1 * 4 + 3][r1] = pa1.w;
            int br = tid >> 2, bq = tid & 3;
            Bs[bq * 4 + 0][br] = pb0.x; Bs[bq * 4 + 1][br] = pb0.y;
            Bs[bq * 4 + 2][br] = pb0.z; Bs[bq * 4 + 3][br] = pb0.w;
        }
        __syncthreads();
        if (kt + 1 < NK) {
            int kb = (kt + 1) * 16;
            int i0 = tid, i1 = tid + 256;
            int r0 = i0 >> 2, q0 = i0 & 3;
            int r1 = i1 >> 2, q1 = i1 & 3;
            pa0 = *(const float4*)&A[(size_t)(m0 + r0) * K + kb + q0 * 4];
            pa1 = *(const float4*)&A[(size_t)(m0 + r1) * K + kb + q1 * 4];
            int br = tid >> 2, bq = tid & 3;
            pb0 = *(const float4*)&Wt[(size_t)(n0 + br) * K + kb + bq * 4];
        }
#pragma unroll
        for (int k = 0; k < 16; k++) {
            ulonglong2 ap0 = *(const ulonglong2*)&As[k][tmg * 8];
            ulonglong2 ap1 = *(const ulonglong2*)&As[k][tmg * 8 + 4];
            float4 bv = *(const float4*)&Bs[k][tn * 4];
            ull ap[4] = {ap0.x, ap0.y, ap1.x, ap1.y};
            ull bb2[4] = {bcast2(bv.x), bcast2(bv.y), bcast2(bv.z), bcast2(bv.w)};
#pragma unroll
            for (int mp = 0; mp < 4; mp++)
#pragma unroll
                for (int n = 0; n < 4; n++) ffma2(acc2[mp][n], ap[mp], bb2[n]);
        }
    }

    // epilogue with bias
    float4 b1 = *(const float4*)&ba[n0 + tn * 4];
    float4 b2 = *(const float4*)&bb[n0 + tn * 4];
    float bias[4] = {b1.x + b2.x, b1.y + b2.y, b1.z + b2.z, b1.w + b2.w};
#pragma unroll
    for (int mp = 0; mp < 4; mp++) {
        float2 c0 = u2f2(acc2[mp][0]);
        float2 c1 = u2f2(acc2[mp][1]);
        float2 c2 = u2f2(acc2[mp][2]);
        float2 c3 = u2f2(acc2[mp][3]);
        float4 olo, ohi;
        olo.x = c0.x + bias[0]; olo.y = c1.x + bias[1];
        olo.z = c2.x + bias[2]; olo.w = c3.x + bias[3];
        ohi.x = c0.y + bias[0]; ohi.y = c1.y + bias[1];
        ohi.z = c2.y + bias[2]; ohi.w = c3.y + bias[3];
        *(float4*)&out[(size_t)(m0 + tmg * 8 + mp * 2 + 0) * Hdim + n0 + tn * 4] = olo;
        *(float4*)&out[(size_t)(m0 + tmg * 8 + mp * 2 + 1) * Hdim + n0 + tn * 4] = ohi;
    }
}

// ============================================================================
// Recurrence: persistent kernel, 128 CTAs x 256 threads. FFMA2 inner loop.
// CTA owns 8 output neurons j0..j0+7. Hidden state global layout: [H][B].
// W slice pre-broadcast in SMEM as (w,w) pairs: w2_s[k][j], 64 KB.
// Threads: bt = tid&7 (b phase group), kl = (tid>>3)&3, kh = tid>>5 (warp).
// Per-thread: 8 b (pairs: bt*4+{0,1},{2,3} and 32+bt*4+{0,1},{2,3}) x 8 j x 32 k.
// ============================================================================
#define RNN_W2_BYTES   (1024 * 8 * 8)          // 64 KB (ull pairs)
#define RNN_HS_FLOATS  (128 * 64)              // one staged chunk [128k][64b]
#define RNN_SMEM_BYTES (RNN_W2_BYTES + 2 * RNN_HS_FLOATS * 4 + 8 * 512 * 4 + 512 * 4)

static __device__ __forceinline__ void stage_h(const float* __restrict__ hin,
                                               int kt, float* dst, int tid) {
#pragma unroll
    for (int r = 0; r < 8; r++) {
        int idx = r * 256 + tid;          // 2048 float4
        int kk = idx >> 4;                // 0..127
        int c4 = idx & 15;                // float4 col within 64-float row
        unsigned d = smem_u32(&dst[kk * 64 + c4 * 4]);
        const float* s = &hin[(kt * 128 + kk) * 64 + c4 * 4];
        asm volatile("cp.async.cg.shared.global [%0], [%1], 16;" ::"r"(d), "l"(s));
    }
}

__global__ void __launch_bounds__(256) rnn_kernel(
    const float* __restrict__ xp, const float* __restrict__ Whh,
    float* __restrict__ out_seq, long long strideB, long long strideT)
{
    extern __shared__ __align__(16) char smraw[];
    ull*   w2_s = (ull*)smraw;                                    // [1024][8] pairs
    float* h_s  = (float*)(smraw + RNN_W2_BYTES);                 // [2][128][64]
    float* p_s  = (float*)(smraw + RNN_W2_BYTES + 2 * RNN_HS_FLOATS * 4); // [8][512]
    float* v_s  = p_s + 8 * 512;                                  // [8][64]

    const int tid = threadIdx.x;
    const int bt  = tid & 7;
    const int kl  = (tid >> 3) & 3;
    const int kh  = tid >> 5;
    const int j0  = blockIdx.x * 8;
    const int nb  = gridDim.x;

    // build pre-broadcast W pairs in SMEM: w2_s[k*8+j] = (W[j0+j][k], same)
    for (int idx = tid; idx < 8192; idx += 256) {
        int j = idx >> 10, k = idx & 1023;
        w2_s[k * 8 + j] = bcast2(Whh[(size_t)(j0 + j) * Hdim + k]);
    }
    // zero initial hidden state slice (rows j0..j0+7 of [H][B])
    if (tid < 128)
        *(float4*)&g_hbuf[0][j0 * 64 + tid * 4] = make_float4(0.f, 0.f, 0.f, 0.f);
    grid_sync(nb);

    // output mapping for the reduce/epilogue: o = 2*tid (+1): same jl, b & b+1
    const int jl = (2 * tid) >> 6;
    const int bo = (2 * tid) & 63;

    for (int t = 0; t < Sdim; t++) {
        const float* hin = g_hbuf[t & 1];
        float* hout = g_hbuf[(t + 1) & 1];

        // early xp prefetch (consumed ~4000 cyc later in the epilogue)
        float xpv0, xpv1;
        {
            const float* xpp = xp + (size_t)bo * strideB + (size_t)t * strideT + j0 + jl;
            asm("ld.global.f32 %0, [%1];" : "=f"(xpv0) : "l"(xpp));
            asm("ld.global.f32 %0, [%1];" : "=f"(xpv1) : "l"(xpp + strideB));
        }

        ull acc[4][8];
#pragma unroll
        for (int i = 0; i < 4; i++)
#pragma unroll
            for (int j = 0; j < 8; j++) acc[i][j] = 0ull;

        stage_h(hin, 0, h_s, tid);
        asm volatile("cp.async.commit_group;");

#pragma unroll 1
        for (int kt = 0; kt < 8; kt++) {
            if (kt < 7) {
                stage_h(hin, kt + 1, h_s + ((kt + 1) & 1) * RNN_HS_FLOATS, tid);
                asm volatile("cp.async.commit_group;");
                asm volatile("cp.async.wait_group 1;");
            } else {
                asm volatile("cp.async.wait_group 0;");
            }
            __syncthreads();

            const float* hb = h_s + (kt & 1) * RNN_HS_FLOATS;
#pragma unroll
            for (int ii = 0; ii < 4; ii++) {
                int kk = ii * 32 + kh * 4 + kl;
                const float* hrow = hb + kk * 64;
                ulonglong2 hA = *(const ulonglong2*)(hrow + bt * 4);
                ulonglong2 hB = *(const ulonglong2*)(hrow + 32 + bt * 4);
                const ull* wr = w2_s + (size_t)(kt * 128 + kk) * 8;
                ulonglong2 w01 = *(const ulonglong2*)(wr + 0);
                ulonglong2 w23 = *(const ulonglong2*)(wr + 2);
                ulonglong2 w45 = *(const ulonglong2*)(wr + 4);
                ulonglong2 w67 = *(const ulonglong2*)(wr + 6);
                ull hp[4] = {hA.x, hA.y, hB.x, hB.y};
                ull wb[8] = {w01.x, w01.y, w23.x, w23.y, w45.x, w45.y, w67.x, w67.y};
#pragma unroll
                for (int bp = 0; bp < 4; bp++)
#pragma unroll
                    for (int j = 0; j < 8; j++) ffma2(acc[bp][j], hp[bp], wb[j]);
            }
            __syncthreads();
        }

        // reduce over kl (4 lanes apart by 8, 16) via shfl + packed add
#pragma unroll
        for (int bp = 0; bp < 4; bp++)
#pragma unroll
            for (int j = 0; j < 8; j++) {
                ull v = acc[bp][j];
                v = addf32x2(v, __shfl_xor_sync(0xFFFFFFFFu, v, 8));
                v = addf32x2(v, __shfl_xor_sync(0xFFFFFFFFu, v, 16));
                acc[bp][j] = v;
            }
        // per-warp partials into SMEM (kl==0 lanes), layout p_s[warp][j*64+b]
        if (kl == 0) {
#pragma unroll
            for (int bp = 0; bp < 4; bp++) {
                int b = (bp < 2) ? (bt * 4 + bp * 2) : (32 + bt * 4 + (bp - 2) * 2);
#pragma unroll
                for (int j = 0; j < 8; j++)
                    *(ull*)&p_s[kh * 512 + j * 64 + b] = acc[bp][j];
            }
        }
        __syncthreads();

        // final: sum 8 warps, add xp, tanh, write hout [H][B] + v_s
        {
            ull s = *(const ull*)&p_s[jl * 64 + bo];
#pragma unroll
            for (int w = 1; w < 8; w++)
                s = addf32x2(s, *(const ull*)&p_s[w * 512 + jl * 64 + bo]);
            float2 sv = u2f2(s);
            float v0 = tanhf(sv.x + xpv0);
            float v1 = tanhf(sv.y + xpv1);
            *(float2*)&hout[(j0 + jl) * 64 + bo] = make_float2(v0, v1);
            *(float2*)&v_s[jl * 64 + bo] = make_float2(v0, v1);
        }

        if (out_seq) {
            __syncthreads();
            // coalesced sequence write: out_seq layout [t][b][H]
            int b2 = tid >> 2;
            int jj = (tid & 3) * 2;
            float va = v_s[jj * 64 + b2];
            float vb = v_s[(jj + 1) * 64 + b2];
            *(float2*)&out_seq[((size_t)t * Bdim + b2) * Hdim + j0 + jj] =
                make_float2(va, vb);
        }
        grid_sync(nb);
    }
}

// ============================================================================
// Final FC + sigmoid: out[b] = sigmoid(dot(h_last[.][b], fc_w) + fc_b)
// hlast layout: [H][B]
// ============================================================================
__global__ void fc_kernel(const float* __restrict__ hlast,
                          const float* __restrict__ fcw,
                          const float* __restrict__ fcb,
                          float* __restrict__ out)
{
    __shared__ float red[8];
    int b = blockIdx.x, tid = threadIdx.x;
    float s = 0.0f;
    for (int k = tid; k < Hdim; k += 256) s += hlast[k * 64 + b] * fcw[k];
#pragma unroll
    for (int o = 16; o; o >>= 1) s += __shfl_xor_sync(0xFFFFFFFFu, s, o);
    if ((tid & 31) == 0) red[tid >> 5] = s;
    __syncthreads();
    if (tid == 0) {
        float tot = 0.0f;
#pragma unroll
        for (int i = 0; i < 8; i++) tot += red[i];
        float logit = tot + fcb[0];
        out[b] = 1.0f / (1.0f + expf(-logit));
    }
}

// ============================================================================
extern "C" void kernel_launch(void* const* d_in, const int* in_sizes, int n_in,
                              void* d_out, int out_size)
{
    const float* x     = (const float*)d_in[0];
    const float* W_ih0 = (const float*)d_in[1];
    const float* W_hh0 = (const float*)d_in[2];
    const float* b_ih0 = (const float*)d_in[3];
    const float* b_hh0 = (const float*)d_in[4];
    const float* W_ih1 = (const float*)d_in[5];
    const float* W_hh1 = (const float*)d_in[6];
    const float* b_ih1 = (const float*)d_in[7];
    const float* b_hh1 = (const float*)d_in[8];
    const float* fc_w  = (const float*)d_in[9];
    const float* fc_b  = (const float*)d_in[10];
    float* out = (float*)d_out;

    float *xp, *h1, *hbuf;
    cudaGetSymbolAddress((void**)&xp, g_xp);
    cudaGetSymbolAddress((void**)&h1, g_h1);
    cudaGetSymbolAddress((void**)&hbuf, g_hbuf);

    cudaFuncSetAttribute(rnn_kernel, cudaFuncAttributeMaxDynamicSharedMemorySize,
                         RNN_SMEM_BYTES);

    dim3 ggrid(16, 256);  // N/64, M/128

    // layer 0: xp rows are m = b*S + s  -> xp[(b*S+t)*H + j]
    xproj_kernel<Fdim><<<ggrid, 256>>>(x, W_ih0, b_ih0, b_hh0, xp);
    rnn_kernel<<<128, 256, RNN_SMEM_BYTES>>>(xp, W_hh0, h1,
                                             (long long)Sdim * Hdim, (long long)Hdim);
    // layer 1: h1 is [t][b][H] -> xproj rows m = t*B + b -> xp[(t*B+b)*H + j]
    xproj_kernel<Hdim><<<ggrid, 256>>>(h1, W_ih1, b_ih1, b_hh1, xp);
    rnn_kernel<<<128, 256, RNN_SMEM_BYTES>>>(xp, W_hh1, nullptr,
                                             (long long)Hdim, (long long)Bdim * Hdim);
    // head (final h2 is in g_hbuf[0] since step 511 writes buffer (511+1)&1 = 0)
    fc_kernel<<<64, 256>>>(hbuf, fc_w, fc_b, out);
}

// round 7
// speedup vs baseline: 1.1300x; 1.0983x over previous
#include <cuda_runtime.h>
#include <cuda_bf16.h>
#include <math.h>
#include <stdint.h>

#define Bdim 64
#define Sdim 512
#define Fdim 512
#define Hdim 1024

typedef unsigned long long ull;

// ---------------- scratch (static device globals; no runtime allocation) ----
__device__ float g_xp[(size_t)Bdim * Sdim * Hdim];   // 128 MB: x-projection buffer
__device__ float g_h1[(size_t)Bdim * Sdim * Hdim];   // 128 MB: layer-1 hidden seq [t][b][H]
__device__ float g_hbuf[2][Hdim * Bdim];             // double-buffered hidden state [k][b]
__device__ unsigned g_bar_count = 0;
__device__ volatile unsigned g_bar_gen = 0;

static __device__ __forceinline__ unsigned smem_u32(const void* p) {
    return (unsigned)__cvta_generic_to_shared(p);
}

// ---------------- packed fp32x2 helpers ------------------------------------
static __device__ __forceinline__ void ffma2(ull& d, ull a, ull b) {
    asm("fma.rn.f32x2 %0, %1, %2, %0;" : "+l"(d) : "l"(a), "l"(b));
}
static __device__ __forceinline__ ull addf32x2(ull a, ull b) {
    ull d; asm("add.rn.f32x2 %0, %1, %2;" : "=l"(d) : "l"(a), "l"(b)); return d;
}
static __device__ __forceinline__ ull bcast2(float x) {
    ull d; unsigned r = __float_as_uint(x);
    asm("mov.b64 %0, {%1, %1};" : "=l"(d) : "r"(r)); return d;
}
static __device__ __forceinline__ float2 u2f2(ull v) {
    float2 f; asm("mov.b64 {%0, %1}, %2;" : "=f"(f.x), "=f"(f.y) : "l"(v)); return f;
}

// ---------------- grid barrier (all 128 CTAs co-resident; grid <= 148) ------
static __device__ __forceinline__ void grid_sync(int nblocks) {
    __syncthreads();
    if (threadIdx.x == 0) {
        __threadfence();
        unsigned g = g_bar_gen;
        if (atomicAdd(&g_bar_count, 1u) == (unsigned)(nblocks - 1)) {
            g_bar_count = 0;
            __threadfence();
            g_bar_gen = g + 1;
        } else {
            while (g_bar_gen == g) {}
        }
        __threadfence();
    }
    __syncthreads();
}

// ============================================================================
// xproj via mma.sync (baseline-ISA HMMA, works on compute_103):
//   out[m][n] = sum_k A[m][k]*Wt[n][k] + ba[n] + bb[n]
// bf16 hi/lo split, 3 accumulating passes (Ah*Bh + Ah*Bl + Al*Bh).
// CTA tile 128m x 128n, K-tile 64. 8 warps: warp tile 32m x 64n
// (2 m16 x 8 n8 mma.m16n8k16 per k16). grid = (N/128, M/128).
// ============================================================================
#define SW128(o) ((o) ^ (((o) >> 3) & 0x70))

#define XP_OFF_BIAS 0
#define XP_OFF_AH   1024
#define XP_OFF_AL   (XP_OFF_AH + 16384)
#define XP_OFF_BH   (XP_OFF_AL + 16384)
#define XP_OFF_BL   (XP_OFF_BH + 16384)
#define XP_SMEM     (XP_OFF_BL + 16384)

static __device__ __forceinline__ void ldsm_x4(uint32_t addr, uint32_t* r) {
    asm volatile("ldmatrix.sync.aligned.m8n8.x4.shared.b16 {%0,%1,%2,%3}, [%4];"
                 : "=r"(r[0]), "=r"(r[1]), "=r"(r[2]), "=r"(r[3]) : "r"(addr));
}
static __device__ __forceinline__ void mma16816(float* c, const uint32_t* a,
                                                const uint32_t* b) {
    asm volatile("mma.sync.aligned.m16n8k16.row.col.f32.bf16.bf16.f32 "
                 "{%0,%1,%2,%3}, {%4,%5,%6,%7}, {%8,%9}, {%0,%1,%2,%3};"
                 : "+f"(c[0]), "+f"(c[1]), "+f"(c[2]), "+f"(c[3])
                 : "r"(a[0]), "r"(a[1]), "r"(a[2]), "r"(a[3]),
                   "r"(b[0]), "r"(b[1]));
}
// swizzled ldmatrix row address within a 128-row x 128-byte tile
static __device__ __forceinline__ uint32_t lm_addr(uint32_t base, int r, int ck) {
    return base + r * 128 + ((ck ^ (r & 7)) << 4);
}

template <int K>
__global__ void __launch_bounds__(256, 2) xproj_mma_kernel(
    const float* __restrict__ A, const float* __restrict__ Wt,
    const float* __restrict__ ba, const float* __restrict__ bb,
    float* __restrict__ out)
{
    extern __shared__ __align__(1024) char xsm[];
    const uint32_t sb = smem_u32(xsm);
    const int tid = threadIdx.x;
    const int wid = tid >> 5;
    const int lane = tid & 31;
    const int wm = wid & 3;          // m group: 32 rows each
    const int wn = wid >> 2;         // n group: 64 cols each
    const int m0 = blockIdx.y * 128;
    const int n0 = blockIdx.x * 128;

    float* sbias = (float*)(xsm + XP_OFF_BIAS);
    if (tid < 128) sbias[tid] = ba[n0 + tid] + bb[n0 + tid];

    float acc[2][8][4];
#pragma unroll
    for (int mt = 0; mt < 2; mt++)
#pragma unroll
        for (int nt = 0; nt < 8; nt++)
#pragma unroll
            for (int i = 0; i < 4; i++) acc[mt][nt][i] = 0.0f;

    const int NKT = K / 64;
#pragma unroll 1
    for (int kt = 0; kt < NKT; kt++) {
        __syncthreads();   // previous pass finished reading smem
        const float* Asrc = A + (size_t)m0 * K + kt * 64;
        const float* Bsrc = Wt + (size_t)n0 * K + kt * 64;
#pragma unroll
        for (int r = 0; r < 8; r++) {
            int idx = r * 256 + tid;      // 0..2047
            int row = idx >> 4;           // 0..127
            int c4 = idx & 15;            // float4 col within 64
            int sw = SW128(row * 128 + c4 * 8);

            float4 v = *(const float4*)&Asrc[(size_t)row * K + c4 * 4];
            __nv_bfloat162 h01 = __floats2bfloat162_rn(v.x, v.y);
            __nv_bfloat162 h23 = __floats2bfloat162_rn(v.z, v.w);
            __nv_bfloat162 l01 = __floats2bfloat162_rn(v.x - __low2float(h01),
                                                       v.y - __high2float(h01));
            __nv_bfloat162 l23 = __floats2bfloat162_rn(v.z - __low2float(h23),
                                                       v.w - __high2float(h23));
            *(uint2*)(xsm + XP_OFF_AH + sw) =
                make_uint2(*(unsigned*)&h01, *(unsigned*)&h23);
            *(uint2*)(xsm + XP_OFF_AL + sw) =
                make_uint2(*(unsigned*)&l01, *(unsigned*)&l23);

            float4 w = *(const float4*)&Bsrc[(size_t)row * K + c4 * 4];
            __nv_bfloat162 wh01 = __floats2bfloat162_rn(w.x, w.y);
            __nv_bfloat162 wh23 = __floats2bfloat162_rn(w.z, w.w);
            __nv_bfloat162 wl01 = __floats2bfloat162_rn(w.x - __low2float(wh01),
                                                        w.y - __high2float(wh01));
            __nv_bfloat162 wl23 = __floats2bfloat162_rn(w.z - __low2float(wh23),
                                                        w.w - __high2float(wh23));
            *(uint2*)(xsm + XP_OFF_BH + sw) =
                make_uint2(*(unsigned*)&wh01, *(unsigned*)&wh23);
            *(uint2*)(xsm + XP_OFF_BL + sw) =
                make_uint2(*(unsigned*)&wl01, *(unsigned*)&wl23);
        }
        __syncthreads();

        // A ldmatrix lane mapping: sub = lane>>3
        const int asub = lane >> 3;
        const int arow = (asub & 1) * 8 + (lane & 7);
        const int ack = asub >> 1;
        // B ldmatrix lane mapping: nt_sel = lane>>4, kc = (lane>>3)&1
        const int brow = ((lane >> 4) & 1) * 8 + (lane & 7);
        const int bck = (lane >> 3) & 1;

#pragma unroll
        for (int p = 0; p < 3; p++) {
            uint32_t aBase = sb + ((p == 2) ? XP_OFF_AL : XP_OFF_AH);
            uint32_t bBase = sb + ((p == 1) ? XP_OFF_BL : XP_OFF_BH);
#pragma unroll
            for (int kk = 0; kk < 4; kk++) {
                uint32_t afrag[2][4], bfrag[8][2];
#pragma unroll
                for (int mt = 0; mt < 2; mt++)
                    ldsm_x4(lm_addr(aBase, wm * 32 + mt * 16 + arow, kk * 2 + ack),
                            afrag[mt]);
#pragma unroll
                for (int np = 0; np < 4; np++) {
                    uint32_t r4[4];
                    ldsm_x4(lm_addr(bBase, wn * 64 + np * 16 + brow, kk * 2 + bck), r4);
                    bfrag[np * 2][0] = r4[0]; bfrag[np * 2][1] = r4[1];
                    bfrag[np * 2 + 1][0] = r4[2]; bfrag[np * 2 + 1][1] = r4[3];
                }
#pragma unroll
                for (int mt = 0; mt < 2; mt++)
#pragma unroll
                    for (int nt = 0; nt < 8; nt++)
                        mma16816(acc[mt][nt], afrag[mt], bfrag[nt]);
            }
        }
    }

    // epilogue: D frag thread l: rows (l>>2), (l>>2)+8; cols (l&3)*2, +1
#pragma unroll
    for (int mt = 0; mt < 2; mt++) {
#pragma unroll
        for (int nt = 0; nt < 8; nt++) {
            int m = m0 + wm * 32 + mt * 16 + (lane >> 2);
            int nl = wn * 64 + nt * 8 + (lane & 3) * 2;
            float2 o0, o1;
            o0.x = acc[mt][nt][0] + sbias[nl];
            o0.y = acc[mt][nt][1] + sbias[nl + 1];
            o1.x = acc[mt][nt][2] + sbias[nl];
            o1.y = acc[mt][nt][3] + sbias[nl + 1];
            *(float2*)&out[(size_t)m * Hdim + n0 + nl] = o0;
            *(float2*)&out[(size_t)(m + 8) * Hdim + n0 + nl] = o1;
        }
    }
}

// ============================================================================
// Recurrence: persistent kernel, 128 CTAs x 256 threads. (unchanged from R5)
// ============================================================================
#define RNN_W2_BYTES   (1024 * 8 * 8)          // 64 KB (ull pairs)
#define RNN_HS_FLOATS  (128 * 64)              // one staged chunk [128k][64b]
#define RNN_SMEM_BYTES (RNN_W2_BYTES + 2 * RNN_HS_FLOATS * 4 + 8 * 512 * 4 + 512 * 4)

static __device__ __forceinline__ void stage_h(const float* __restrict__ hin,
                                               int kt, float* dst, int tid) {
#pragma unroll
    for (int r = 0; r < 8; r++) {
        int idx = r * 256 + tid;          // 2048 float4
        int kk = idx >> 4;                // 0..127
        int c4 = idx & 15;                // float4 col within 64-float row
        unsigned d = smem_u32(&dst[kk * 64 + c4 * 4]);
        const float* s = &hin[(kt * 128 + kk) * 64 + c4 * 4];
        asm volatile("cp.async.cg.shared.global [%0], [%1], 16;" ::"r"(d), "l"(s));
    }
}

__global__ void __launch_bounds__(256) rnn_kernel(
    const float* __restrict__ xp, const float* __restrict__ Whh,
    float* __restrict__ out_seq, long long strideB, long long strideT)
{
    extern __shared__ __align__(16) char smraw[];
    ull*   w2_s = (ull*)smraw;                                    // [1024][8] pairs
    float* h_s  = (float*)(smraw + RNN_W2_BYTES);                 // [2][128][64]
    float* p_s  = (float*)(smraw + RNN_W2_BYTES + 2 * RNN_HS_FLOATS * 4); // [8][512]
    float* v_s  = p_s + 8 * 512;                                  // [8][64]

    const int tid = threadIdx.x;
    const int bt  = tid & 7;
    const int kl  = (tid >> 3) & 3;
    const int kh  = tid >> 5;
    const int j0  = blockIdx.x * 8;
    const int nb  = gridDim.x;

    for (int idx = tid; idx < 8192; idx += 256) {
        int j = idx >> 10, k = idx & 1023;
        w2_s[k * 8 + j] = bcast2(Whh[(size_t)(j0 + j) * Hdim + k]);
    }
    if (tid < 128)
        *(float4*)&g_hbuf[0][j0 * 64 + tid * 4] = make_float4(0.f, 0.f, 0.f, 0.f);
    grid_sync(nb);

    const int jl = (2 * tid) >> 6;
    const int bo = (2 * tid) & 63;

    for (int t = 0; t < Sdim; t++) {
        const float* hin = g_hbuf[t & 1];
        float* hout = g_hbuf[(t + 1) & 1];

        float xpv0, xpv1;
        {
            const float* xpp = xp + (size_t)bo * strideB + (size_t)t * strideT + j0 + jl;
            asm("ld.global.f32 %0, [%1];" : "=f"(xpv0) : "l"(xpp));
            asm("ld.global.f32 %0, [%1];" : "=f"(xpv1) : "l"(xpp + strideB));
        }

        ull acc[4][8];
#pragma unroll
        for (int i = 0; i < 4; i++)
#pragma unroll
            for (int j = 0; j < 8; j++) acc[i][j] = 0ull;

        stage_h(hin, 0, h_s, tid);
        asm volatile("cp.async.commit_group;");

#pragma unroll 1
        for (int kt = 0; kt < 8; kt++) {
            if (kt < 7) {
                stage_h(hin, kt + 1, h_s + ((kt + 1) & 1) * RNN_HS_FLOATS, tid);
                asm volatile("cp.async.commit_group;");
                asm volatile("cp.async.wait_group 1;");
            } else {
                asm volatile("cp.async.wait_group 0;");
            }
            __syncthreads();

            const float* hb = h_s + (kt & 1) * RNN_HS_FLOATS;
#pragma unroll
            for (int ii = 0; ii < 4; ii++) {
                int kk = ii * 32 + kh * 4 + kl;
                const float* hrow = hb + kk * 64;
                ulonglong2 hA = *(const ulonglong2*)(hrow + bt * 4);
                ulonglong2 hB = *(const ulonglong2*)(hrow + 32 + bt * 4);
                const ull* wr = w2_s + (size_t)(kt * 128 + kk) * 8;
                ulonglong2 w01 = *(const ulonglong2*)(wr + 0);
                ulonglong2 w23 = *(const ulonglong2*)(wr + 2);
                ulonglong2 w45 = *(const ulonglong2*)(wr + 4);
                ulonglong2 w67 = *(const ulonglong2*)(wr + 6);
                ull hp[4] = {hA.x, hA.y, hB.x, hB.y};
                ull wb[8] = {w01.x, w01.y, w23.x, w23.y, w45.x, w45.y, w67.x, w67.y};
#pragma unroll
                for (int bp = 0; bp < 4; bp++)
#pragma unroll
                    for (int j = 0; j < 8; j++) ffma2(acc[bp][j], hp[bp], wb[j]);
            }
            __syncthreads();
        }

#pragma unroll
        for (int bp = 0; bp < 4; bp++)
#pragma unroll
            for (int j = 0; j < 8; j++) {
                ull v = acc[bp][j];
                v = addf32x2(v, __shfl_xor_sync(0xFFFFFFFFu, v, 8));
                v = addf32x2(v, __shfl_xor_sync(0xFFFFFFFFu, v, 16));
                acc[bp][j] = v;
            }
        if (kl == 0) {
#pragma unroll
            for (int bp = 0; bp < 4; bp++) {
                int b = (bp < 2) ? (bt * 4 + bp * 2) : (32 + bt * 4 + (bp - 2) * 2);
#pragma unroll
                for (int j = 0; j < 8; j++)
                    *(ull*)&p_s[kh * 512 + j * 64 + b] = acc[bp][j];
            }
        }
        __syncthreads();

        {
            ull s = *(const ull*)&p_s[jl * 64 + bo];
#pragma unroll
            for (int w = 1; w < 8; w++)
                s = addf32x2(s, *(const ull*)&p_s[w * 512 + jl * 64 + bo]);
            float2 sv = u2f2(s);
            float v0 = tanhf(sv.x + xpv0);
            float v1 = tanhf(sv.y + xpv1);
            *(float2*)&hout[(j0 + jl) * 64 + bo] = make_float2(v0, v1);
            *(float2*)&v_s[jl * 64 + bo] = make_float2(v0, v1);
        }

        if (out_seq) {
            __syncthreads();
            int b2 = tid >> 2;
            int jj = (tid & 3) * 2;
            float va = v_s[jj * 64 + b2];
            float vb = v_s[(jj + 1) * 64 + b2];
            *(float2*)&out_seq[((size_t)t * Bdim + b2) * Hdim + j0 + jj] =
                make_float2(va, vb);
        }
        grid_sync(nb);
    }
}

// ============================================================================
// Final FC + sigmoid: out[b] = sigmoid(dot(h_last[.][b], fc_w) + fc_b)
// ============================================================================
__global__ void fc_kernel(const float* __restrict__ hlast,
                          const float* __restrict__ fcw,
                          const float* __restrict__ fcb,
                          float* __restrict__ out)
{
    __shared__ float red[8];
    int b = blockIdx.x, tid = threadIdx.x;
    float s = 0.0f;
    for (int k = tid; k < Hdim; k += 256) s += hlast[k * 64 + b] * fcw[k];
#pragma unroll
    for (int o = 16; o; o >>= 1) s += __shfl_xor_sync(0xFFFFFFFFu, s, o);
    if ((tid & 31) == 0) red[tid >> 5] = s;
    __syncthreads();
    if (tid == 0) {
        float tot = 0.0f;
#pragma unroll
        for (int i = 0; i < 8; i++) tot += red[i];
        float logit = tot + fcb[0];
        out[b] = 1.0f / (1.0f + expf(-logit));
    }
}

// ============================================================================
extern "C" void kernel_launch(void* const* d_in, const int* in_sizes, int n_in,
                              void* d_out, int out_size)
{
    const float* x     = (const float*)d_in[0];
    const float* W_ih0 = (const float*)d_in[1];
    const float* W_hh0 = (const float*)d_in[2];
    const float* b_ih0 = (const float*)d_in[3];
    const float* b_hh0 = (const float*)d_in[4];
    const float* W_ih1 = (const float*)d_in[5];
    const float* W_hh1 = (const float*)d_in[6];
    const float* b_ih1 = (const float*)d_in[7];
    const float* b_hh1 = (const float*)d_in[8];
    const float* fc_w  = (const float*)d_in[9];
    const float* fc_b  = (const float*)d_in[10];
    float* out = (float*)d_out;

    float *xp, *h1, *hbuf;
    cudaGetSymbolAddress((void**)&xp, g_xp);
    cudaGetSymbolAddress((void**)&h1, g_h1);
    cudaGetSymbolAddress((void**)&hbuf, g_hbuf);

    cudaFuncSetAttribute(rnn_kernel, cudaFuncAttributeMaxDynamicSharedMemorySize,
                         RNN_SMEM_BYTES);
    cudaFuncSetAttribute(xproj_mma_kernel<Fdim>,
                         cudaFuncAttributeMaxDynamicSharedMemorySize, XP_SMEM);
    cudaFuncSetAttribute(xproj_mma_kernel<Hdim>,
                         cudaFuncAttributeMaxDynamicSharedMemorySize, XP_SMEM);

    dim3 xgrid(8, 256);  // n-tiles x m-tiles

    // layer 0: xp rows are m = b*S + t  -> xp[(b*S+t)*H + j]
    xproj_mma_kernel<Fdim><<<xgrid, 256, XP_SMEM>>>(x, W_ih0, b_ih0, b_hh0, xp);
    rnn_kernel<<<128, 256, RNN_SMEM_BYTES>>>(xp, W_hh0, h1,
                                             (long long)Sdim * Hdim, (long long)Hdim);
    // layer 1: h1 is [t][b][H] -> rows m = t*B + b -> xp[(t*B+b)*H + j]
    xproj_mma_kernel<Hdim><<<xgrid, 256, XP_SMEM>>>(h1, W_ih1, b_ih1, b_hh1, xp);
    rnn_kernel<<<128, 256, RNN_SMEM_BYTES>>>(xp, W_hh1, nullptr,
                                             (long long)Hdim, (long long)Bdim * Hdim);
    // head (final h2 is in g_hbuf[0] since step 511 writes buffer (511+1)&1 = 0)
    fc_kernel<<<64, 256>>>(hbuf, fc_w, fc_b, out);
}

// round 8
// speedup vs baseline: 1.5708x; 1.3901x over previous
#include <cuda_runtime.h>
#include <cuda_bf16.h>
#include <math.h>
#include <stdint.h>

#define Bdim 64
#define Sdim 512
#define Fdim 512
#define Hdim 1024

// ---------------- scratch (static device globals; no runtime allocation) ----
__device__ float g_xp[(size_t)Bdim * Sdim * Hdim];   // 128 MB: x-projection buffer
__device__ float g_h1[(size_t)Bdim * Sdim * Hdim];   // 128 MB: layer-1 hidden seq [t][b][H]
__device__ __nv_bfloat16 g_hh[2][Bdim * Hdim];       // hidden state hi, [b][k], dbl-buf
__device__ __nv_bfloat16 g_hl[2][Bdim * Hdim];       // hidden state lo
__device__ unsigned g_bar_count = 0;
__device__ volatile unsigned g_bar_gen = 0;

static __device__ __forceinline__ unsigned smem_u32(const void* p) {
    return (unsigned)__cvta_generic_to_shared(p);
}

// ---------------- grid barrier (all CTAs co-resident; grid <= 148) ----------
static __device__ __forceinline__ void grid_sync(int nblocks) {
    __syncthreads();
    if (threadIdx.x == 0) {
        __threadfence();
        unsigned g = g_bar_gen;
        if (atomicAdd(&g_bar_count, 1u) == (unsigned)(nblocks - 1)) {
            g_bar_count = 0;
            __threadfence();
            g_bar_gen = g + 1;
        } else {
            while (g_bar_gen == g) {}
        }
        __threadfence();
    }
    __syncthreads();
}

// ---------------- mma.sync helpers (baseline ISA, compile for compute_103) --
static __device__ __forceinline__ void ldsm_x4(uint32_t addr, uint32_t* r) {
    asm volatile("ldmatrix.sync.aligned.m8n8.x4.shared.b16 {%0,%1,%2,%3}, [%4];"
                 : "=r"(r[0]), "=r"(r[1]), "=r"(r[2]), "=r"(r[3]) : "r"(addr));
}
static __device__ __forceinline__ void mma16816(float* c, const uint32_t* a,
                                                const uint32_t* b) {
    asm volatile("mma.sync.aligned.m16n8k16.row.col.f32.bf16.bf16.f32 "
                 "{%0,%1,%2,%3}, {%4,%5,%6,%7}, {%8,%9}, {%0,%1,%2,%3};"
                 : "+f"(c[0]), "+f"(c[1]), "+f"(c[2]), "+f"(c[3])
                 : "r"(a[0]), "r"(a[1]), "r"(a[2]), "r"(a[3]),
                   "r"(b[0]), "r"(b[1]));
}

// ============================================================================
// xproj via mma.sync: out[m][n] = sum_k A[m][k]*Wt[n][k] + ba[n] + bb[n]
// bf16 hi/lo split, 3 accumulating passes. (unchanged from R7 — passing)
// ============================================================================
#define SW128(o) ((o) ^ (((o) >> 3) & 0x70))

#define XP_OFF_BIAS 0
#define XP_OFF_AH   1024
#define XP_OFF_AL   (XP_OFF_AH + 16384)
#define XP_OFF_BH   (XP_OFF_AL + 16384)
#define XP_OFF_BL   (XP_OFF_BH + 16384)
#define XP_SMEM     (XP_OFF_BL + 16384)

// swizzled ldmatrix row address within a 128-row x 128-byte tile
static __device__ __forceinline__ uint32_t lm_addr(uint32_t base, int r, int ck) {
    return base + r * 128 + ((ck ^ (r & 7)) << 4);
}

template <int K>
__global__ void __launch_bounds__(256, 2) xproj_mma_kernel(
    const float* __restrict__ A, const float* __restrict__ Wt,
    const float* __restrict__ ba, const float* __restrict__ bb,
    float* __restrict__ out)
{
    extern __shared__ __align__(1024) char xsm[];
    const uint32_t sb = smem_u32(xsm);
    const int tid = threadIdx.x;
    const int wid = tid >> 5;
    const int lane = tid & 31;
    const int wm = wid & 3;          // m group: 32 rows each
    const int wn = wid >> 2;         // n group: 64 cols each
    const int m0 = blockIdx.y * 128;
    const int n0 = blockIdx.x * 128;

    float* sbias = (float*)(xsm + XP_OFF_BIAS);
    if (tid < 128) sbias[tid] = ba[n0 + tid] + bb[n0 + tid];

    float acc[2][8][4];
#pragma unroll
    for (int mt = 0; mt < 2; mt++)
#pragma unroll
        for (int nt = 0; nt < 8; nt++)
#pragma unroll
            for (int i = 0; i < 4; i++) acc[mt][nt][i] = 0.0f;

    const int NKT = K / 64;
#pragma unroll 1
    for (int kt = 0; kt < NKT; kt++) {
        __syncthreads();
        const float* Asrc = A + (size_t)m0 * K + kt * 64;
        const float* Bsrc = Wt + (size_t)n0 * K + kt * 64;
#pragma unroll
        for (int r = 0; r < 8; r++) {
            int idx = r * 256 + tid;
            int row = idx >> 4;
            int c4 = idx & 15;
            int sw = SW128(row * 128 + c4 * 8);

            float4 v = *(const float4*)&Asrc[(size_t)row * K + c4 * 4];
            __nv_bfloat162 h01 = __floats2bfloat162_rn(v.x, v.y);
            __nv_bfloat162 h23 = __floats2bfloat162_rn(v.z, v.w);
            __nv_bfloat162 l01 = __floats2bfloat162_rn(v.x - __low2float(h01),
                                                       v.y - __high2float(h01));
            __nv_bfloat162 l23 = __floats2bfloat162_rn(v.z - __low2float(h23),
                                                       v.w - __high2float(h23));
            *(uint2*)(xsm + XP_OFF_AH + sw) =
                make_uint2(*(unsigned*)&h01, *(unsigned*)&h23);
            *(uint2*)(xsm + XP_OFF_AL + sw) =
                make_uint2(*(unsigned*)&l01, *(unsigned*)&l23);

            float4 w = *(const float4*)&Bsrc[(size_t)row * K + c4 * 4];
            __nv_bfloat162 wh01 = __floats2bfloat162_rn(w.x, w.y);
            __nv_bfloat162 wh23 = __floats2bfloat162_rn(w.z, w.w);
            __nv_bfloat162 wl01 = __floats2bfloat162_rn(w.x - __low2float(wh01),
                                                        w.y - __high2float(wh01));
            __nv_bfloat162 wl23 = __floats2bfloat162_rn(w.z - __low2float(wh23),
                                                        w.w - __high2float(wh23));
            *(uint2*)(xsm + XP_OFF_BH + sw) =
                make_uint2(*(unsigned*)&wh01, *(unsigned*)&wh23);
            *(uint2*)(xsm + XP_OFF_BL + sw) =
                make_uint2(*(unsigned*)&wl01, *(unsigned*)&wl23);
        }
        __syncthreads();

        const int asub = lane >> 3;
        const int arow = (asub & 1) * 8 + (lane & 7);
        const int ack = asub >> 1;
        const int brow = ((lane >> 4) & 1) * 8 + (lane & 7);
        const int bck = (lane >> 3) & 1;

#pragma unroll
        for (int p = 0; p < 3; p++) {
            uint32_t aBase = sb + ((p == 2) ? XP_OFF_AL : XP_OFF_AH);
            uint32_t bBase = sb + ((p == 1) ? XP_OFF_BL : XP_OFF_BH);
#pragma unroll
            for (int kk = 0; kk < 4; kk++) {
                uint32_t afrag[2][4], bfrag[8][2];
#pragma unroll
                for (int mt = 0; mt < 2; mt++)
                    ldsm_x4(lm_addr(aBase, wm * 32 + mt * 16 + arow, kk * 2 + ack),
                            afrag[mt]);
#pragma unroll
                for (int np = 0; np < 4; np++) {
                    uint32_t r4[4];
                    ldsm_x4(lm_addr(bBase, wn * 64 + np * 16 + brow, kk * 2 + bck), r4);
                    bfrag[np * 2][0] = r4[0]; bfrag[np * 2][1] = r4[1];
                    bfrag[np * 2 + 1][0] = r4[2]; bfrag[np * 2 + 1][1] = r4[3];
                }
#pragma unroll
                for (int mt = 0; mt < 2; mt++)
#pragma unroll
                    for (int nt = 0; nt < 8; nt++)
                        mma16816(acc[mt][nt], afrag[mt], bfrag[nt]);
            }
        }
    }

#pragma unroll
    for (int mt = 0; mt < 2; mt++) {
#pragma unroll
        for (int nt = 0; nt < 8; nt++) {
            int m = m0 + wm * 32 + mt * 16 + (lane >> 2);
            int nl = wn * 64 + nt * 8 + (lane & 3) * 2;
            float2 o0, o1;
            o0.x = acc[mt][nt][0] + sbias[nl];
            o0.y = acc[mt][nt][1] + sbias[nl + 1];
            o1.x = acc[mt][nt][2] + sbias[nl];
            o1.y = acc[mt][nt][3] + sbias[nl + 1];
            *(float2*)&out[(size_t)m * Hdim + n0 + nl] = o0;
            *(float2*)&out[(size_t)(m + 8) * Hdim + n0 + nl] = o1;
        }
    }
}

// ============================================================================
// Recurrence via mma.sync: persistent, 64 CTAs x 256 threads.
// CTA owns 16 output neurons j0..j0+15. Per step:
//   C[64b x 16j] = h[64 x 1024] @ Whh_slice^T  (bf16 hi/lo, 3-pass)
//   h_new = tanh(C + xp)
// h kept globally as bf16 hi+lo [b][k]. Warp w = k-slice of 128.
// SMEM: W hi/lo 64KB | stage buf0 64KB | stage buf1 64KB  (192 KB)
// Cross-warp partials alias stage buf0 (written after all MMAs of the step).
// ============================================================================
#define RNN_OFF_W    0
#define RNN_OFF_S0   65536
#define RNN_OFF_S1   131072
#define RNN_SMEM_BYTES 196608

// stage chunk kc (256 k-values) of h (hi+lo) into stage buffer
static __device__ __forceinline__ void stage_h2(
    const __nv_bfloat16* __restrict__ hh, const __nv_bfloat16* __restrict__ hl,
    int kc, char* dst, int tid)
{
#pragma unroll
    for (int r = 0; r < 8; r++) {
        int idx = r * 256 + tid;          // 0..2047
        int b = idx >> 5;                 // 0..63
        int lg = idx & 31;                // 16B granule within 512B row
        uint32_t d = smem_u32(dst + b * 512 + ((lg ^ (b & 7)) << 4));
        const __nv_bfloat16* s = hh + b * Hdim + kc * 256 + lg * 8;
        asm volatile("cp.async.cg.shared.global [%0], [%1], 16;" ::"r"(d), "l"(s));
        const __nv_bfloat16* s2 = hl + b * Hdim + kc * 256 + lg * 8;
        asm volatile("cp.async.cg.shared.global [%0], [%1], 16;"
                     ::"r"(d + 32768), "l"(s2));
    }
}

__global__ void __launch_bounds__(256) rnn_kernel(
    const float* __restrict__ xp, const float* __restrict__ Whh,
    float* __restrict__ out_seq, long long strideB, long long strideT)
{
    extern __shared__ __align__(1024) char smraw[];
    const int tid = threadIdx.x;
    const int wid = tid >> 5;      // warp = k-slice (128 k each)
    const int lane = tid & 31;
    const int j0 = blockIdx.x * 16;
    const int nb = gridDim.x;

    const uint32_t whbase = smem_u32(smraw + RNN_OFF_W);       // W hi
    const uint32_t wlbase = whbase + 32768;                    // W lo
    float* p_s = (float*)(smraw + RNN_OFF_S0);                 // partials alias

    // ---- load W slice (16 x 1024 fp32) -> bf16 hi/lo swizzled SMEM ----
    for (int i = tid; i < 4096; i += 256) {       // float4 units
        int j = i >> 8;                           // 0..15
        int col4 = i & 255;                       // float4 col
        float4 v = *(const float4*)&Whh[(size_t)(j0 + j) * Hdim + col4 * 4];
        __nv_bfloat162 h01 = __floats2bfloat162_rn(v.x, v.y);
        __nv_bfloat162 h23 = __floats2bfloat162_rn(v.z, v.w);
        __nv_bfloat162 l01 = __floats2bfloat162_rn(v.x - __low2float(h01),
                                                   v.y - __high2float(h01));
        __nv_bfloat162 l23 = __floats2bfloat162_rn(v.z - __low2float(h23),
                                                   v.w - __high2float(h23));
        int g = col4 >> 1;
        int off = j * 2048 + ((g ^ (j & 7)) << 4) + (col4 & 1) * 8;
        *(uint2*)(smraw + RNN_OFF_W + off) =
            make_uint2(*(unsigned*)&h01, *(unsigned*)&h23);
        *(uint2*)(smraw + RNN_OFF_W + 32768 + off) =
            make_uint2(*(unsigned*)&l01, *(unsigned*)&l23);
    }
    // zero initial hidden state slice (cols j0..j0+15 of [b][k], both parities use p0)
    if (tid < 64) {
        *(uint4*)&g_hh[0][tid * Hdim + j0] = make_uint4(0, 0, 0, 0);
        *(uint4*)&g_hl[0][tid * Hdim + j0] = make_uint4(0, 0, 0, 0);
    }
    grid_sync(nb);

    // ldmatrix lane mappings (same proven pattern as xproj)
    const int asub = lane >> 3;
    const int arow = (asub & 1) * 8 + (lane & 7);
    const int ack = asub >> 1;
    const int brow = ((lane >> 4) & 1) * 8 + (lane & 7);   // 0..15 (16 W rows)
    const int bck = (lane >> 3) & 1;

    // epilogue mapping: thread handles outputs o = tid*4 .. +3
    const int eb = tid >> 2;            // batch row
    const int ej = (tid & 3) * 4;       // j within 16

#pragma unroll 1
    for (int t = 0; t < Sdim; t++) {
        const __nv_bfloat16* hh_in = g_hh[t & 1];
        const __nv_bfloat16* hl_in = g_hl[t & 1];
        __nv_bfloat16* hh_out = g_hh[(t + 1) & 1];
        __nv_bfloat16* hl_out = g_hl[(t + 1) & 1];

        // early xp prefetch
        float4 xpv = *(const float4*)&xp[(size_t)eb * strideB + (size_t)t * strideT
                                         + j0 + ej];

        float acc[4][2][4];
#pragma unroll
        for (int mt = 0; mt < 4; mt++)
#pragma unroll
            for (int nt = 0; nt < 2; nt++)
#pragma unroll
                for (int i = 0; i < 4; i++) acc[mt][nt][i] = 0.0f;

        stage_h2(hh_in, hl_in, 0, smraw + RNN_OFF_S0, tid);
        asm volatile("cp.async.commit_group;");
        stage_h2(hh_in, hl_in, 1, smraw + RNN_OFF_S1, tid);
        asm volatile("cp.async.commit_group;");

#pragma unroll
        for (int c = 0; c < 4; c++) {
            if (c < 3) asm volatile("cp.async.wait_group 1;");
            else       asm volatile("cp.async.wait_group 0;");
            __syncthreads();

            const uint32_t shbase = smem_u32(smraw +
                ((c & 1) ? RNN_OFF_S1 : RNN_OFF_S0));
            const uint32_t slbase = shbase + 32768;

#pragma unroll
            for (int s2 = 0; s2 < 2; s2++) {
                // A frags: 4 m-tiles, hi + lo
                uint32_t ah[4][4], al[4][4];
                int gA = wid * 4 + s2 * 2 + ack;           // granule 0..31
#pragma unroll
                for (int mt = 0; mt < 4; mt++) {
                    int row = mt * 16 + arow;
                    uint32_t sw = (uint32_t)((gA ^ (row & 7)) << 4);
                    ldsm_x4(shbase + row * 512 + sw, ah[mt]);
                    ldsm_x4(slbase + row * 512 + sw, al[mt]);
                }
                // B frags from W: k16 index global within 1024
                int sg = c * 16 + wid * 2 + s2;            // 0..63
                int gB = sg * 2 + bck;                     // granule 0..127
                uint32_t bh[4], bl[4];
                uint32_t bsw = (uint32_t)((gB ^ (brow & 7)) << 4);
                ldsm_x4(whbase + brow * 2048 + bsw, bh);
                ldsm_x4(wlbase + brow * 2048 + bsw, bl);

#pragma unroll
                for (int mt = 0; mt < 4; mt++) {
                    mma16816(acc[mt][0], ah[mt], &bh[0]);
                    mma16816(acc[mt][1], ah[mt], &bh[2]);
                    mma16816(acc[mt][0], ah[mt], &bl[0]);
                    mma16816(acc[mt][1], ah[mt], &bl[2]);
                    mma16816(acc[mt][0], al[mt], &bh[0]);
                    mma16816(acc[mt][1], al[mt], &bh[2]);
                }
            }
            __syncthreads();
            if (c + 2 < 4) {
                stage_h2(hh_in, hl_in, c + 2,
                         smraw + ((c & 1) ? RNN_OFF_S1 : RNN_OFF_S0), tid);
                asm volatile("cp.async.commit_group;");
            }
        }

        // ---- cross-warp reduce: partials p_s[w][b*16+j] (aliases stage buf0) ----
#pragma unroll
        for (int mt = 0; mt < 4; mt++)
#pragma unroll
            for (int nt = 0; nt < 2; nt++) {
                int b = mt * 16 + (lane >> 2);
                int j = nt * 8 + (lane & 3) * 2;
                *(float2*)&p_s[wid * 1024 + b * 16 + j] =
                    make_float2(acc[mt][nt][0], acc[mt][nt][1]);
                *(float2*)&p_s[wid * 1024 + (b + 8) * 16 + j] =
                    make_float2(acc[mt][nt][2], acc[mt][nt][3]);
            }
        __syncthreads();

        {
            int o = tid * 4;
            float4 s = *(const float4*)&p_s[o];
#pragma unroll
            for (int w = 1; w < 8; w++) {
                float4 q = *(const float4*)&p_s[w * 1024 + o];
                s.x += q.x; s.y += q.y; s.z += q.z; s.w += q.w;
            }
            float v0 = tanhf(s.x + xpv.x);
            float v1 = tanhf(s.y + xpv.y);
            float v2 = tanhf(s.z + xpv.z);
            float v3 = tanhf(s.w + xpv.w);

            __nv_bfloat162 h01 = __floats2bfloat162_rn(v0, v1);
            __nv_bfloat162 h23 = __floats2bfloat162_rn(v2, v3);
            __nv_bfloat162 l01 = __floats2bfloat162_rn(v0 - __low2float(h01),
                                                       v1 - __high2float(h01));
            __nv_bfloat162 l23 = __floats2bfloat162_rn(v2 - __low2float(h23),
                                                       v3 - __high2float(h23));
            size_t ho = (size_t)eb * Hdim + j0 + ej;
            *(uint2*)&hh_out[ho] = make_uint2(*(unsigned*)&h01, *(unsigned*)&h23);
            *(uint2*)&hl_out[ho] = make_uint2(*(unsigned*)&l01, *(unsigned*)&l23);
            if (out_seq)
                *(float4*)&out_seq[((size_t)t * Bdim + eb) * Hdim + j0 + ej] =
                    make_float4(v0, v1, v2, v3);
        }
        grid_sync(nb);
    }
}

// ============================================================================
// Final FC + sigmoid: out[b] = sigmoid(dot(h_last[b], fc_w) + fc_b)
// h_last = g_hh[0] + g_hl[0] (bf16 hi/lo, [b][k])
// ============================================================================
__global__ void fc_kernel(const __nv_bfloat16* __restrict__ hh,
                          const __nv_bfloat16* __restrict__ hl,
                          const float* __restrict__ fcw,
                          const float* __restrict__ fcb,
                          float* __restrict__ out)
{
    __shared__ float red[8];
    int b = blockIdx.x, tid = threadIdx.x;
    float s = 0.0f;
    for (int k = tid; k < Hdim; k += 256) {
        float h = __bfloat162float(hh[b * Hdim + k]) +
                  __bfloat162float(hl[b * Hdim + k]);
        s += h * fcw[k];
    }
#pragma unroll
    for (int o = 16; o; o >>= 1) s += __shfl_xor_sync(0xFFFFFFFFu, s, o);
    if ((tid & 31) == 0) red[tid >> 5] = s;
    __syncthreads();
    if (tid == 0) {
        float tot = 0.0f;
#pragma unroll
        for (int i = 0; i < 8; i++) tot += red[i];
        float logit = tot + fcb[0];
        out[b] = 1.0f / (1.0f + expf(-logit));
    }
}

// ============================================================================
extern "C" void kernel_launch(void* const* d_in, const int* in_sizes, int n_in,
                              void* d_out, int out_size)
{
    const float* x     = (const float*)d_in[0];
    const float* W_ih0 = (const float*)d_in[1];
    const float* W_hh0 = (const float*)d_in[2];
    const float* b_ih0 = (const float*)d_in[3];
    const float* b_hh0 = (const float*)d_in[4];
    const float* W_ih1 = (const float*)d_in[5];
    const float* W_hh1 = (const float*)d_in[6];
    const float* b_ih1 = (const float*)d_in[7];
    const float* b_hh1 = (const float*)d_in[8];
    const float* fc_w  = (const float*)d_in[9];
    const float* fc_b  = (const float*)d_in[10];
    float* out = (float*)d_out;

    float *xp, *h1;
    __nv_bfloat16 *hh, *hl;
    cudaGetSymbolAddress((void**)&xp, g_xp);
    cudaGetSymbolAddress((void**)&h1, g_h1);
    cudaGetSymbolAddress((void**)&hh, g_hh);
    cudaGetSymbolAddress((void**)&hl, g_hl);

    cudaFuncSetAttribute(rnn_kernel, cudaFuncAttributeMaxDynamicSharedMemorySize,
                         RNN_SMEM_BYTES);
    cudaFuncSetAttribute(xproj_mma_kernel<Fdim>,
                         cudaFuncAttributeMaxDynamicSharedMemorySize, XP_SMEM);
    cudaFuncSetAttribute(xproj_mma_kernel<Hdim>,
                         cudaFuncAttributeMaxDynamicSharedMemorySize, XP_SMEM);

    dim3 xgrid(8, 256);  // n-tiles x m-tiles

    // layer 0: xp rows are m = b*S + t  -> xp[(b*S+t)*H + j]
    xproj_mma_kernel<Fdim><<<xgrid, 256, XP_SMEM>>>(x, W_ih0, b_ih0, b_hh0, xp);
    rnn_kernel<<<64, 256, RNN_SMEM_BYTES>>>(xp, W_hh0, h1,
                                            (long long)Sdim * Hdim, (long long)Hdim);
    // layer 1: h1 is [t][b][H] -> rows m = t*B + b -> xp[(t*B+b)*H + j]
    xproj_mma_kernel<Hdim><<<xgrid, 256, XP_SMEM>>>(h1, W_ih1, b_ih1, b_hh1, xp);
    rnn_kernel<<<64, 256, RNN_SMEM_BYTES>>>(xp, W_hh1, nullptr,
                                            (long long)Hdim, (long long)Bdim * Hdim);
    // head (final h2 parity 0: step 511 writes buffer (511+1)&1 = 0)
    fc_kernel<<<64, 256>>>(hh, hl, fc_w, fc_b, out);
}